// round 8
// baseline (speedup 1.0000x reference)
#include <cuda_runtime.h>
#include <math.h>
#include <stdint.h>

// Problem constants (fixed by the reference)
#define Nn 20000
#define Ee 320000
#define Dd 128
#define Kk 8
#define Hh 64
#define Ll 3
#define FULL 0xffffffffu

// -------- device scratch (static globals; no allocation) --------
__device__ float g_S[(size_t)Nn * Kk * Dd];   // 81.92 MB  per-node weighted sums (tf32-rounded)
__device__ float g_Wt[Dd * Kk * Hh];          // 256 KB    W_enc rounded to tf32
__device__ float g_v[Kk * Dd];                // folded (W_enc*attn_l)/3  (k-major)
__device__ int   g_deg[Nn];
__device__ int   g_beg[Nn];
__device__ int   g_cur[Nn];
__device__ int   g_perm[Ee];
__device__ int   g_ctr;

__device__ __forceinline__ float tf32_rna(float x) {
    uint32_t r;
    asm("cvt.rna.tf32.f32 %0, %1;" : "=r"(r) : "f"(x));
    return __uint_as_float(r);
}

// ---------------------------------------------------------------
// K0: fold v[k][d] = (1/3)*sum_h W_enc[d,kH+h]*attn_l[k,h];
//     round W_enc into g_Wt (tf32 rna); zero deg/ctr
// ---------------------------------------------------------------
__global__ void k_prep(const float* __restrict__ We, const float* __restrict__ al) {
    __shared__ float al_sh[Kk * Hh];
    int t = threadIdx.x;                // 1024 threads
    if (t < Kk * Hh) al_sh[t] = al[t];
    for (int i = t; i < Nn; i += 1024) g_deg[i] = 0;
    for (int i = t; i < Dd * Kk * Hh; i += 1024) g_Wt[i] = tf32_rna(We[i]);
    if (t == 0) g_ctr = 0;
    __syncthreads();
    int k = t >> 7;
    int d = t & 127;
    const float* wrow = We + (size_t)d * (Kk * Hh) + k * Hh;
    const float* arow = al_sh + k * Hh;
    float s = 0.f;
#pragma unroll 8
    for (int h = 0; h < Hh; ++h) s = fmaf(wrow[h], arow[h], s);
    g_v[k * Dd + d] = s * (1.f / 3.f);
}

// ---------------------------------------------------------------
// K1: histogram of dst
// ---------------------------------------------------------------
__global__ void k_hist(const int* __restrict__ dst) {
    int e = blockIdx.x * blockDim.x + threadIdx.x;
    if (e < Ee) atomicAdd(&g_deg[dst[e]], 1);
}

// ---------------------------------------------------------------
// K2: order-free offset assignment: warp prefix + one atomicAdd/warp.
// ---------------------------------------------------------------
__global__ void k_off() {
    int n = blockIdx.x * blockDim.x + threadIdx.x;
    int lane = threadIdx.x & 31;
    int d = (n < Nn) ? g_deg[n] : 0;
    int pre = d;
#pragma unroll
    for (int o = 1; o < 32; o <<= 1) {
        int u = __shfl_up_sync(FULL, pre, o);
        if (lane >= o) pre += u;
    }
    int tot = __shfl_sync(FULL, pre, 31);
    int base = 0;
    if (lane == 31) base = atomicAdd(&g_ctr, tot);
    base = __shfl_sync(FULL, base, 31);
    int beg = base + pre - d;
    if (n < Nn) { g_beg[n] = beg; g_cur[n] = beg; }
}

// ---------------------------------------------------------------
// K3: scatter edge ids into per-dst contiguous ranges
// ---------------------------------------------------------------
__global__ void k_scatter(const int* __restrict__ dst) {
    int e = blockIdx.x * blockDim.x + threadIdx.x;
    if (e < Ee) {
        int pos = atomicAdd(&g_cur[dst[e]], 1);
        g_perm[pos] = e;
    }
}

// ---------------------------------------------------------------
// 9-shuffle reduction of 8 per-lane partials over the warp.
// Lane ends with full sum of value k(lane) = bitrev3(lane&7).
// Inverse map (source lane for k): SRC = {0,4,2,6,1,5,3,7}
// ---------------------------------------------------------------
__device__ __forceinline__ float reduce8_fast(float v[8], int lane) {
    bool b0 = lane & 1;
    float q0 = b0 ? v[4] : v[0], r0 = b0 ? v[0] : v[4];
    float q1 = b0 ? v[5] : v[1], r1 = b0 ? v[1] : v[5];
    float q2 = b0 ? v[6] : v[2], r2 = b0 ? v[2] : v[6];
    float q3 = b0 ? v[7] : v[3], r3 = b0 ? v[3] : v[7];
    q0 += __shfl_xor_sync(FULL, r0, 1);
    q1 += __shfl_xor_sync(FULL, r1, 1);
    q2 += __shfl_xor_sync(FULL, r2, 1);
    q3 += __shfl_xor_sync(FULL, r3, 1);
    bool b1 = lane & 2;
    float s0 = b1 ? q2 : q0, t0 = b1 ? q0 : q2;
    float s1 = b1 ? q3 : q1, t1 = b1 ? q1 : q3;
    s0 += __shfl_xor_sync(FULL, t0, 2);
    s1 += __shfl_xor_sync(FULL, t1, 2);
    bool b2 = lane & 4;
    float u0 = b2 ? s1 : s0, u1 = b2 ? s0 : s1;
    u0 += __shfl_xor_sync(FULL, u1, 4);
    u0 += __shfl_xor_sync(FULL, u0, 8);
    u0 += __shfl_xor_sync(FULL, u0, 16);
    return u0;
}

// ---------------------------------------------------------------
// K4: warp-per-node fused pass.  Register-resident, no smem/blocksyncs.
// Lane owns d = 4*lane..4*lane+3.  No max-subtraction softmax (logits
// are O(1); exp safe in fp32; softmax shift-invariant).
// Depth-3 software pipeline (3 edges in flight).
// S stored tf32-rounded for the tensor-core GEMM.
// ---------------------------------------------------------------
__global__ __launch_bounds__(128, 4) void k_agg(const float* __restrict__ ef,
                                                const float* __restrict__ nf,
                                                const float* __restrict__ Wr) {
    int t = threadIdx.x, lane = t & 31, w = t >> 5;
    int n = blockIdx.x * 4 + w;
    if (n >= Nn) return;

    float4 vv[Kk];
#pragma unroll
    for (int k = 0; k < Kk; ++k)
        vv[k] = ((const float4*)(g_v + k * Dd))[lane];

    float er_ln;
    {
        float4 x = ((const float4*)(nf + (size_t)n * Dd))[lane];
        float tk[Kk];
#pragma unroll
        for (int k = 0; k < Kk; ++k) {
            float4 wk = ((const float4*)(Wr + k * Dd))[lane];
            float s = x.x * wk.x;
            s = fmaf(x.y, wk.y, s);
            s = fmaf(x.z, wk.z, s);
            s = fmaf(x.w, wk.w, s);
            tk[k] = s;
        }
        er_ln = reduce8_fast(tk, lane);
    }

    float4 sl[Kk];
#pragma unroll
    for (int k = 0; k < Kk; ++k) sl[k] = make_float4(0.f, 0.f, 0.f, 0.f);
    float l_run = 0.f;

    int beg = g_beg[n];
    int end = beg + g_deg[n];

#define LOADE(idx, A, B, C) do {                                             \
        int eid = g_perm[(idx)];                                             \
        const float4* src = (const float4*)(ef + (size_t)eid * (Ll * Dd));   \
        A = __ldcs(src + lane);                                              \
        B = __ldcs(src + lane + 32);                                         \
        C = __ldcs(src + lane + 64);                                         \
    } while (0)

#define STEP(EA, EB, EC) do {                                                \
        float4 s4;                                                           \
        s4.x = EA.x + EB.x + EC.x;                                           \
        s4.y = EA.y + EB.y + EC.y;                                           \
        s4.z = EA.z + EB.z + EC.z;                                           \
        s4.w = EA.w + EB.w + EC.w;                                           \
        float tk[Kk];                                                        \
        _Pragma("unroll")                                                    \
        for (int k = 0; k < Kk; ++k) {                                       \
            float s = s4.x * vv[k].x;                                        \
            s = fmaf(s4.y, vv[k].y, s);                                      \
            s = fmaf(s4.z, vv[k].z, s);                                      \
            s = fmaf(s4.w, vv[k].w, s);                                      \
            tk[k] = s;                                                       \
        }                                                                    \
        float e = reduce8_fast(tk, lane) + er_ln;                            \
        e = (e > 0.f) ? e : 0.01f * e;                                       \
        float p = __expf(e);                                                 \
        l_run += p;                                                          \
        _Pragma("unroll")                                                    \
        for (int k = 0; k < Kk; ++k) {                                       \
            float pk = __shfl_sync(FULL, p, SRC[k]);                         \
            sl[k].x = fmaf(pk, s4.x, sl[k].x);                               \
            sl[k].y = fmaf(pk, s4.y, sl[k].y);                               \
            sl[k].z = fmaf(pk, s4.z, sl[k].z);                               \
            sl[k].w = fmaf(pk, s4.w, sl[k].w);                               \
        }                                                                    \
    } while (0)

    constexpr int SRC[8] = {0, 4, 2, 6, 1, 5, 3, 7};

    float4 A0, B0, C0, A1, B1, C1, A2, B2, C2;
    if (beg < end)     LOADE(beg,     A0, B0, C0);
    if (beg + 1 < end) LOADE(beg + 1, A1, B1, C1);
    if (beg + 2 < end) LOADE(beg + 2, A2, B2, C2);

    int i = beg;
    while (i < end) {
        {
            float4 ea = A0, eb = B0, ec = C0;
            if (i + 3 < end) LOADE(i + 3, A0, B0, C0);
            STEP(ea, eb, ec);
        }
        if (++i >= end) break;
        {
            float4 ea = A1, eb = B1, ec = C1;
            if (i + 3 < end) LOADE(i + 3, A1, B1, C1);
            STEP(ea, eb, ec);
        }
        if (++i >= end) break;
        {
            float4 ea = A2, eb = B2, ec = C2;
            if (i + 3 < end) LOADE(i + 3, A2, B2, C2);
            STEP(ea, eb, ec);
        }
        ++i;
    }
#undef LOADE
#undef STEP

    float inv = (l_run > 0.f) ? (1.f / l_run) : 0.f;
#pragma unroll
    for (int k = 0; k < Kk; ++k) {
        float ik = __shfl_sync(FULL, inv, SRC[k]) * (1.f / 3.f);
        float4 o;
        o.x = tf32_rna(sl[k].x * ik);
        o.y = tf32_rna(sl[k].y * ik);
        o.z = tf32_rna(sl[k].z * ik);
        o.w = tf32_rna(sl[k].w * ik);
        ((float4*)(g_S + ((size_t)n * Kk + k) * Dd))[lane] = o;
    }
}

// ---------------------------------------------------------------
// K5: out[n,k,:] = S[n,k,:] @ W_enc[:, kH:kH+H]  via tf32 mma.sync.
// Block: 64 nodes x 64 h for head kk.  4 warps; warp owns 16 nodes.
// Smem padded for conflict-free fragment loads:
//   Ss stride 68 -> A-frag banks 4r+c (distinct)
//   Ws stride 72 -> B-frag banks 8k+h (distinct)
// ---------------------------------------------------------------
__global__ __launch_bounds__(128) void k_gemm(float* __restrict__ out) {
    __shared__ float Ss[64][68];      // 17.4 KB
    __shared__ float Ws[64][72];      // 18.4 KB
    int t = threadIdx.x, lane = t & 31, w = t >> 5;
    int kk = blockIdx.y;
    int n0 = blockIdx.x * 64;

    float c[8][4];
#pragma unroll
    for (int j = 0; j < 8; ++j)
#pragma unroll
        for (int q = 0; q < 4; ++q) c[j][q] = 0.f;

#pragma unroll
    for (int c2 = 0; c2 < 2; ++c2) {
        __syncthreads();
        // Ss: thread t -> row t>>1, half t&1 (8 float4 = 32 floats)
        {
            int row = t >> 1, half = t & 1;
            int n = n0 + row;
            float* drow = &Ss[row][half * 32];
            if (n < Nn) {
                const float4* src = (const float4*)(g_S + ((size_t)n * Kk + kk) * Dd
                                                    + c2 * 64 + half * 32);
#pragma unroll
                for (int j = 0; j < 8; ++j) ((float4*)drow)[j] = src[j];
            } else {
#pragma unroll
                for (int j = 0; j < 8; ++j) ((float4*)drow)[j] = make_float4(0, 0, 0, 0);
            }
        }
        // Ws: 4096 floats = 1024 float4; i = t + 128*j ; k = i>>4, hq = i&15
#pragma unroll
        for (int j = 0; j < 8; ++j) {
            int i = t + 128 * j;
            int k = i >> 4, hq = i & 15;
            *((float4*)&Ws[k][hq * 4]) =
                *((const float4*)(g_Wt + (size_t)(c2 * 64 + k) * (Kk * Hh)
                                  + kk * Hh + hq * 4));
        }
        __syncthreads();

#pragma unroll
        for (int q = 0; q < 8; ++q) {
            int r0 = w * 16 + (lane >> 2);
            int cA = q * 8 + (lane & 3);
            uint32_t a0 = __float_as_uint(Ss[r0][cA]);
            uint32_t a1 = __float_as_uint(Ss[r0 + 8][cA]);
            uint32_t a2 = __float_as_uint(Ss[r0][cA + 4]);
            uint32_t a3 = __float_as_uint(Ss[r0 + 8][cA + 4]);
            int kB = q * 8 + (lane & 3);
            int hB = lane >> 2;
#pragma unroll
            for (int j = 0; j < 8; ++j) {
                uint32_t b0 = __float_as_uint(Ws[kB][j * 8 + hB]);
                uint32_t b1 = __float_as_uint(Ws[kB + 4][j * 8 + hB]);
                asm volatile(
                    "mma.sync.aligned.m16n8k8.row.col.f32.tf32.tf32.f32 "
                    "{%0,%1,%2,%3}, {%4,%5,%6,%7}, {%8,%9}, {%0,%1,%2,%3};\n"
                    : "+f"(c[j][0]), "+f"(c[j][1]), "+f"(c[j][2]), "+f"(c[j][3])
                    : "r"(a0), "r"(a1), "r"(a2), "r"(a3), "r"(b0), "r"(b1));
            }
        }
    }

    // epilogue: c[j]: rows w*16 + lane/4 (+8), cols j*8 + 2*(lane&3) (+1)
    int rA = n0 + w * 16 + (lane >> 2);
    int colb = kk * Hh + 2 * (lane & 3);
#pragma unroll
    for (int j = 0; j < 8; ++j) {
        int col = colb + j * 8;
        if (rA < Nn)
            *((float2*)(out + (size_t)rA * (Kk * Hh) + col)) = make_float2(c[j][0], c[j][1]);
        if (rA + 8 < Nn)
            *((float2*)(out + (size_t)(rA + 8) * (Kk * Hh) + col)) = make_float2(c[j][2], c[j][3]);
    }
}

// ---------------------------------------------------------------
extern "C" void kernel_launch(void* const* d_in, const int* in_sizes, int n_in,
                              void* d_out, int out_size) {
    const float* node_feat = (const float*)d_in[0];   // (N,128)
    const float* edge_feat = (const float*)d_in[1];   // (E,3,128)
    const float* W_enc     = (const float*)d_in[2];   // (128,512)
    const float* attn_l    = (const float*)d_in[3];   // (1,8,64)
    const float* W_r       = (const float*)d_in[4];   // (8,128)
    const int*   dst       = (const int*)  d_in[5];   // (E,)
    float*       out       = (float*)d_out;           // (N,8,64)

    k_prep<<<1, 1024>>>(W_enc, attn_l);
    k_hist<<<(Ee + 255) / 256, 256>>>(dst);
    k_off<<<(Nn + 255) / 256, 256>>>();
    k_scatter<<<(Ee + 255) / 256, 256>>>(dst);
    k_agg<<<(Nn + 3) / 4, 128>>>(edge_feat, node_feat, W_r);
    k_gemm<<<dim3((Nn + 63) / 64, Kk), 128>>>(out);
}